// round 8
// baseline (speedup 1.0000x reference)
#include <cuda_runtime.h>
#include <cuda_fp16.h>
#include <cstdint>

#define N_NODES 100000
#define N_EDGES 1000000
#define H 128

// Scratch: per-node transformed features in fp16 (u = W1_src*z_src + b1, v = W1_dst*z_dst)
__device__ __half g_u[(size_t)N_NODES * H];
__device__ __half g_v[(size_t)N_NODES * H];

#define MT 128
#define NT 128
#define KT 32

// ---- f32x2 packed helpers (SASS FFMA2 path, PTX-only) ----
__device__ __forceinline__ void ffma2(unsigned long long& d,
                                      unsigned long long a,
                                      unsigned long long b) {
    asm("fma.rn.f32x2 %0, %1, %2, %0;" : "+l"(d) : "l"(a), "l"(b));
}
__device__ __forceinline__ unsigned long long pack2(float x, float y) {
    unsigned long long r;
    asm("mov.b64 %0, {%1, %2};" : "=l"(r) : "f"(x), "f"(y));
    return r;
}
__device__ __forceinline__ void unpack2(unsigned long long v, float& x, float& y) {
    asm("mov.b64 {%0, %1}, %2;" : "=f"(x), "=f"(y) : "l"(v));
}

// Tiled fp32 GEMM with packed f32x2 FMA, duplicated-A smem, XOR-swizzled banks.
// out[m,n] = sum_k A[m,k] * W[n, koff+k]   (W row stride 2H), output stored fp16.
// blockIdx.y == 0: A=z_src, koff=0, out=g_u (+b1);  ==1: A=z_dst, koff=H, out=g_v
// Thread (tx=tid&15, ty=tid>>4):
//   rows m = mbase + 2*ty + 32*g + {0,1}, g=0..3 ; cols n = 2*tx + 32*j + {0,1}, j=0..3
__global__ __launch_bounds__(256)
void node_gemm_kernel(const float* __restrict__ zsrc,
                      const float* __restrict__ zdst,
                      const float* __restrict__ W1,
                      const float* __restrict__ b1)
{
    // As2: per (k,m) the duplicated pair (A[m][k], A[m][k]) at 64-bit word
    //      index k*128 + (m ^ (k&15))          -> 32 KB
    // Bs : floats, pair (n,n+1) at 64-bit word index
    //      k*64 + ((n/2) ^ (k&15))             -> 16 KB
    __shared__ __align__(16) unsigned long long As2[KT * 128];
    __shared__ __align__(16) unsigned long long Bs[KT * 64];

    const int tid = threadIdx.x;
    const int tx = tid & 15;
    const int ty = tid >> 4;
    const int mbase = blockIdx.x * MT;
    const bool is_src = (blockIdx.y == 0);
    const float* __restrict__ A = is_src ? zsrc : zdst;
    const float* __restrict__ W = W1 + (is_src ? 0 : H);
    __half* __restrict__ out = is_src ? g_u : g_v;

    unsigned long long acc[8][4];
    #pragma unroll
    for (int r = 0; r < 8; ++r)
        #pragma unroll
        for (int j = 0; j < 4; ++j)
            acc[r][j] = 0ULL;

    float* Bsf = (float*)Bs;

    for (int k0 = 0; k0 < H; k0 += KT) {
        // Stage A tile [MT x KT], duplicated. Coalesced gmem (k fast),
        // swizzled STS.64: bank = (m ^ (k&15)) % 16 -> distinct across k.
        #pragma unroll
        for (int l = 0; l < (MT * KT) / 256; ++l) {
            int idx = tid + l * 256;
            int m = idx >> 5;
            int k = idx & 31;
            int mg = mbase + m;
            float val = (mg < N_NODES) ? A[(size_t)mg * H + (k0 + k)] : 0.f;
            As2[k * 128 + (m ^ (k & 15))] = pack2(val, val);
        }
        // Stage B tile [NT x KT]. Swizzled STS.32 (pair-preserving xor).
        #pragma unroll
        for (int l = 0; l < (NT * KT) / 256; ++l) {
            int idx = tid + l * 256;
            int n = idx >> 5;
            int k = idx & 31;
            // float position inside pair word ((n>>1) ^ (k&15)), half n&1
            Bsf[(k * 64 + ((n >> 1) ^ (k & 15))) * 2 + (n & 1)] =
                W[(size_t)n * (2 * H) + (k0 + k)];
        }
        __syncthreads();

        #pragma unroll
        for (int kk = 0; kk < KT; ++kk) {
            unsigned long long ap[8];
            #pragma unroll
            for (int g = 0; g < 4; ++g) {
                #pragma unroll
                for (int b = 0; b < 2; ++b)
                    ap[2 * g + b] = As2[kk * 128 + ((2 * ty + 32 * g + b) ^ (kk & 15))];
            }
            unsigned long long bp[4];
            #pragma unroll
            for (int j = 0; j < 4; ++j)
                bp[j] = Bs[kk * 64 + ((tx + 16 * j) ^ (kk & 15))];

            #pragma unroll
            for (int r = 0; r < 8; ++r)
                #pragma unroll
                for (int j = 0; j < 4; ++j)
                    ffma2(acc[r][j], ap[r], bp[j]);
        }
        __syncthreads();
    }

    // Epilogue: fold b1 into u, convert to fp16, store half2
    #pragma unroll
    for (int r = 0; r < 8; ++r) {
        int g = r >> 1;
        int m = mbase + 2 * ty + 32 * g + (r & 1);
        if (m < N_NODES) {
            #pragma unroll
            for (int j = 0; j < 4; ++j) {
                int n = 2 * tx + 32 * j;
                float lo, hi;
                unpack2(acc[r][j], lo, hi);
                if (is_src) { lo += b1[n]; hi += b1[n + 1]; }
                __half2 hv = __float22half2_rn(make_float2(lo, hi));
                *(__half2*)&out[(size_t)m * H + n] = hv;
            }
        }
    }
}

// 4 edges per warp: out[e] = W2 . relu(u[row[e]] + v[col[e]]) + b2
// u,v fp16 (row = 256B); lane handles features [4*lane .. 4*lane+3].
__global__ __launch_bounds__(256)
void edge_kernel(const int* __restrict__ eidx,
                 const float* __restrict__ W2,
                 const float* __restrict__ b2,
                 float* __restrict__ out)
{
    const int lane = threadIdx.x & 31;
    const int w = (int)((blockIdx.x * blockDim.x + threadIdx.x) >> 5);
    const int e0 = w * 4;
    if (e0 >= N_EDGES) return;

    const float4 wv = ((const float4*)W2)[lane];
    const int4 r4 = *(const int4*)&eidx[e0];
    const int4 c4 = *(const int4*)&eidx[N_EDGES + e0];

    const uint2* __restrict__ up = (const uint2*)g_u;  // row = 32 uint2
    const uint2* __restrict__ vp = (const uint2*)g_v;

    uint2 ua[4], va[4];
    ua[0] = up[(size_t)r4.x * 32 + lane];
    ua[1] = up[(size_t)r4.y * 32 + lane];
    ua[2] = up[(size_t)r4.z * 32 + lane];
    ua[3] = up[(size_t)r4.w * 32 + lane];
    va[0] = vp[(size_t)c4.x * 32 + lane];
    va[1] = vp[(size_t)c4.y * 32 + lane];
    va[2] = vp[(size_t)c4.z * 32 + lane];
    va[3] = vp[(size_t)c4.w * 32 + lane];

    float s[4];
    #pragma unroll
    for (int i = 0; i < 4; ++i) {
        float2 u01 = __half22float2(*(const __half2*)&ua[i].x);
        float2 u23 = __half22float2(*(const __half2*)&ua[i].y);
        float2 v01 = __half22float2(*(const __half2*)&va[i].x);
        float2 v23 = __half22float2(*(const __half2*)&va[i].y);
        s[i] = fmaxf(u01.x + v01.x, 0.f) * wv.x
             + fmaxf(u01.y + v01.y, 0.f) * wv.y
             + fmaxf(u23.x + v23.x, 0.f) * wv.z
             + fmaxf(u23.y + v23.y, 0.f) * wv.w;
    }

    #pragma unroll
    for (int off = 16; off; off >>= 1) {
        s[0] += __shfl_xor_sync(0xffffffffu, s[0], off);
        s[1] += __shfl_xor_sync(0xffffffffu, s[1], off);
        s[2] += __shfl_xor_sync(0xffffffffu, s[2], off);
        s[3] += __shfl_xor_sync(0xffffffffu, s[3], off);
    }

    if (lane == 0) {
        const float bb = b2[0];
        float4 o = make_float4(s[0] + bb, s[1] + bb, s[2] + bb, s[3] + bb);
        *(float4*)&out[e0] = o;
    }
}

extern "C" void kernel_launch(void* const* d_in, const int* in_sizes, int n_in,
                              void* d_out, int out_size)
{
    const float* zsrc = (const float*)d_in[0];
    const float* zdst = (const float*)d_in[1];
    const int*   eidx = (const int*)d_in[2];
    const float* W1   = (const float*)d_in[3];
    const float* b1   = (const float*)d_in[4];
    const float* W2   = (const float*)d_in[5];
    const float* b2   = (const float*)d_in[6];
    float*       out  = (float*)d_out;

    dim3 ggrid((N_NODES + MT - 1) / MT, 2);
    node_gemm_kernel<<<ggrid, 256>>>(zsrc, zdst, W1, b1);

    const int edges_per_block = (256 / 32) * 4;   // 32 edges/block
    const int eblocks = (N_EDGES + edges_per_block - 1) / edges_per_block;
    edge_kernel<<<eblocks, 256>>>(eidx, W2, b2, out);
}

// round 12
// speedup vs baseline: 2.1310x; 2.1310x over previous
#include <cuda_runtime.h>
#include <cuda_fp16.h>
#include <mma.h>
#include <cstdint>

using namespace nvcuda;

#define N_NODES 100000
#define N_EDGES 1000000
#define H 128

// Scratch: per-node transformed features in fp16 (u = W1_src*z_src + b1, v = W1_dst*z_dst)
__device__ __half g_u[(size_t)N_NODES * H];
__device__ __half g_v[(size_t)N_NODES * H];

// ---- dynamic smem layout ----
// Phase 1: A fp16 [128][136]  at 0       (34816 B)
//          B fp16 [128][136]  at 34816   (34816 B)
// Phase 2: C f32  [128][132]  at 0       (67584 B)  -- union with A/B
// b1 f32 [128] at 69632
#define LDA 136
#define LDC 132
#define S_A 0
#define S_B 34816
#define S_C 0
#define S_B1 69632
#define S_TOTAL 70656

// Tensor-core (HMMA/wmma) node GEMM: out[m,n] = sum_k A[m,k] * W[n, koff+k]
// fp16 inputs, fp32 accumulate, fp16 output.
// blockIdx.y==0: A=z_src, koff=0, out=g_u (+b1); ==1: A=z_dst, koff=H, out=g_v
__global__ __launch_bounds__(256)
void node_gemm_wmma(const float* __restrict__ zsrc,
                    const float* __restrict__ zdst,
                    const float* __restrict__ W1,
                    const float* __restrict__ b1)
{
    extern __shared__ __align__(16) char smem[];
    __half* As = (__half*)(smem + S_A);
    __half* Bs = (__half*)(smem + S_B);
    float*  Cs = (float*)(smem + S_C);
    float*  b1s = (float*)(smem + S_B1);

    const int tid = threadIdx.x;
    const int wid = tid >> 5;
    const int mbase = blockIdx.x * 128;
    const bool is_src = (blockIdx.y == 0);
    const float* __restrict__ A = is_src ? zsrc : zdst;
    const float* __restrict__ W = W1 + (is_src ? 0 : H);
    __half* __restrict__ out = is_src ? g_u : g_v;

    if (tid < 128) b1s[tid] = is_src ? b1[tid] : 0.f;

    // ---- stage A tile [128 x 128] fp32 -> fp16, padded row-major ----
    #pragma unroll
    for (int it = 0; it < 8; ++it) {
        int c = tid + it * 256;          // 2048 chunks of 8 cols
        int row = c >> 4;
        int col = (c & 15) * 8;
        float4 f0 = make_float4(0.f, 0.f, 0.f, 0.f), f1 = f0;
        int mg = mbase + row;
        if (mg < N_NODES) {
            const float* src = A + (size_t)mg * H + col;
            f0 = *(const float4*)src;
            f1 = *(const float4*)(src + 4);
        }
        __half2 h0 = __float22half2_rn(make_float2(f0.x, f0.y));
        __half2 h1 = __float22half2_rn(make_float2(f0.z, f0.w));
        __half2 h2 = __float22half2_rn(make_float2(f1.x, f1.y));
        __half2 h3 = __float22half2_rn(make_float2(f1.z, f1.w));
        uint4 q;
        q.x = *(uint32_t*)&h0; q.y = *(uint32_t*)&h1;
        q.z = *(uint32_t*)&h2; q.w = *(uint32_t*)&h3;
        *(uint4*)&As[row * LDA + col] = q;
    }
    // ---- stage B tile [128 x 128]: W rows (stride 2H) ----
    #pragma unroll
    for (int it = 0; it < 8; ++it) {
        int c = tid + it * 256;
        int n = c >> 4;
        int col = (c & 15) * 8;
        const float* src = W + (size_t)n * (2 * H) + col;
        float4 f0 = *(const float4*)src;
        float4 f1 = *(const float4*)(src + 4);
        __half2 h0 = __float22half2_rn(make_float2(f0.x, f0.y));
        __half2 h1 = __float22half2_rn(make_float2(f0.z, f0.w));
        __half2 h2 = __float22half2_rn(make_float2(f1.x, f1.y));
        __half2 h3 = __float22half2_rn(make_float2(f1.z, f1.w));
        uint4 q;
        q.x = *(uint32_t*)&h0; q.y = *(uint32_t*)&h1;
        q.z = *(uint32_t*)&h2; q.w = *(uint32_t*)&h3;
        *(uint4*)&Bs[n * LDA + col] = q;
    }
    __syncthreads();

    // ---- wmma compute: warp (wm, wn) owns rows [wm*64, +64), cols [wn*32, +32) ----
    const int wm = wid & 1;
    const int wn = wid >> 1;

    wmma::fragment<wmma::accumulator, 16, 16, 16, float> acc[4][2];
    #pragma unroll
    for (int i = 0; i < 4; ++i)
        #pragma unroll
        for (int j = 0; j < 2; ++j)
            wmma::fill_fragment(acc[i][j], 0.f);

    #pragma unroll
    for (int ks = 0; ks < 128; ks += 16) {
        wmma::fragment<wmma::matrix_a, 16, 16, 16, __half, wmma::row_major> af[4];
        wmma::fragment<wmma::matrix_b, 16, 16, 16, __half, wmma::col_major> bf[2];
        #pragma unroll
        for (int i = 0; i < 4; ++i)
            wmma::load_matrix_sync(af[i], &As[(wm * 64 + 16 * i) * LDA + ks], LDA);
        #pragma unroll
        for (int j = 0; j < 2; ++j)
            wmma::load_matrix_sync(bf[j], &Bs[(wn * 32 + 16 * j) * LDA + ks], LDA);
        #pragma unroll
        for (int i = 0; i < 4; ++i)
            #pragma unroll
            for (int j = 0; j < 2; ++j)
                wmma::mma_sync(acc[i][j], af[i], bf[j], acc[i][j]);
    }

    __syncthreads();   // done reading As/Bs; Cs aliases them

    #pragma unroll
    for (int i = 0; i < 4; ++i)
        #pragma unroll
        for (int j = 0; j < 2; ++j)
            wmma::store_matrix_sync(&Cs[(wm * 64 + 16 * i) * LDC + wn * 32 + 16 * j],
                                    acc[i][j], LDC, wmma::mem_row_major);
    __syncthreads();

    // ---- epilogue: +b1, convert fp16, store. Thread: row=tid>>1, 64-col half ----
    {
        const int row = tid >> 1;
        const int c0 = (tid & 1) * 64;
        const int m = mbase + row;
        if (m < N_NODES) {
            uint4* dst = (uint4*)(out + (size_t)m * H + c0);
            #pragma unroll
            for (int jj = 0; jj < 8; ++jj) {
                const float* cp = &Cs[row * LDC + c0 + jj * 8];
                const float* bp = &b1s[c0 + jj * 8];
                float4 f0 = *(const float4*)cp;
                float4 f1 = *(const float4*)(cp + 4);
                float4 g0 = *(const float4*)bp;
                float4 g1 = *(const float4*)(bp + 4);
                __half2 h0 = __float22half2_rn(make_float2(f0.x + g0.x, f0.y + g0.y));
                __half2 h1 = __float22half2_rn(make_float2(f0.z + g0.z, f0.w + g0.w));
                __half2 h2 = __float22half2_rn(make_float2(f1.x + g1.x, f1.y + g1.y));
                __half2 h3 = __float22half2_rn(make_float2(f1.z + g1.z, f1.w + g1.w));
                uint4 q;
                q.x = *(uint32_t*)&h0; q.y = *(uint32_t*)&h1;
                q.z = *(uint32_t*)&h2; q.w = *(uint32_t*)&h3;
                dst[jj] = q;
            }
        }
    }
}

// 4 edges per warp: out[e] = W2 . relu(u[row[e]] + v[col[e]]) + b2  (u,v fp16)
__global__ __launch_bounds__(256)
void edge_kernel(const int* __restrict__ eidx,
                 const float* __restrict__ W2,
                 const float* __restrict__ b2,
                 float* __restrict__ out)
{
    const int lane = threadIdx.x & 31;
    const int w = (int)((blockIdx.x * blockDim.x + threadIdx.x) >> 5);
    const int e0 = w * 4;
    if (e0 >= N_EDGES) return;

    const float4 wv = ((const float4*)W2)[lane];
    const int4 r4 = *(const int4*)&eidx[e0];
    const int4 c4 = *(const int4*)&eidx[N_EDGES + e0];

    const uint2* __restrict__ up = (const uint2*)g_u;  // row = 32 uint2
    const uint2* __restrict__ vp = (const uint2*)g_v;

    uint2 ua[4], va[4];
    ua[0] = up[(size_t)r4.x * 32 + lane];
    ua[1] = up[(size_t)r4.y * 32 + lane];
    ua[2] = up[(size_t)r4.z * 32 + lane];
    ua[3] = up[(size_t)r4.w * 32 + lane];
    va[0] = vp[(size_t)c4.x * 32 + lane];
    va[1] = vp[(size_t)c4.y * 32 + lane];
    va[2] = vp[(size_t)c4.z * 32 + lane];
    va[3] = vp[(size_t)c4.w * 32 + lane];

    float s[4];
    #pragma unroll
    for (int i = 0; i < 4; ++i) {
        float2 u01 = __half22float2(*(const __half2*)&ua[i].x);
        float2 u23 = __half22float2(*(const __half2*)&ua[i].y);
        float2 v01 = __half22float2(*(const __half2*)&va[i].x);
        float2 v23 = __half22float2(*(const __half2*)&va[i].y);
        s[i] = fmaxf(u01.x + v01.x, 0.f) * wv.x
             + fmaxf(u01.y + v01.y, 0.f) * wv.y
             + fmaxf(u23.x + v23.x, 0.f) * wv.z
             + fmaxf(u23.y + v23.y, 0.f) * wv.w;
    }

    #pragma unroll
    for (int off = 16; off; off >>= 1) {
        s[0] += __shfl_xor_sync(0xffffffffu, s[0], off);
        s[1] += __shfl_xor_sync(0xffffffffu, s[1], off);
        s[2] += __shfl_xor_sync(0xffffffffu, s[2], off);
        s[3] += __shfl_xor_sync(0xffffffffu, s[3], off);
    }

    if (lane == 0) {
        const float bb = b2[0];
        float4 o = make_float4(s[0] + bb, s[1] + bb, s[2] + bb, s[3] + bb);
        *(float4*)&out[e0] = o;
    }
}

extern "C" void kernel_launch(void* const* d_in, const int* in_sizes, int n_in,
                              void* d_out, int out_size)
{
    const float* zsrc = (const float*)d_in[0];
    const float* zdst = (const float*)d_in[1];
    const int*   eidx = (const int*)d_in[2];
    const float* W1   = (const float*)d_in[3];
    const float* b1   = (const float*)d_in[4];
    const float* W2   = (const float*)d_in[5];
    const float* b2   = (const float*)d_in[6];
    float*       out  = (float*)d_out;

    cudaFuncSetAttribute(node_gemm_wmma, cudaFuncAttributeMaxDynamicSharedMemorySize, S_TOTAL);

    dim3 ggrid((N_NODES + 127) / 128, 2);   // 782 x 2
    node_gemm_wmma<<<ggrid, 256, S_TOTAL>>>(zsrc, zdst, W1, b1);

    const int edges_per_block = (256 / 32) * 4;   // 32 edges/block
    const int eblocks = (N_EDGES + edges_per_block - 1) / edges_per_block;
    edge_kernel<<<eblocks, 256>>>(eidx, W2, b2, out);
}

// round 13
// speedup vs baseline: 2.4917x; 1.1692x over previous
#include <cuda_runtime.h>
#include <cuda_fp16.h>
#include <mma.h>
#include <cstdint>

using namespace nvcuda;

#define N_NODES 100000
#define N_EDGES 1000000
#define H 128

// Scratch: per-node transformed features in fp16 (u = W1_src*z_src + b1, v = W1_dst*z_dst)
__device__ __half g_u[(size_t)N_NODES * H];
__device__ __half g_v[(size_t)N_NODES * H];

// ---- dynamic smem layout ----
// A fp16 [128][136] at 0        (34816 B)
// B fp16 [128][136] at 34816    (34816 B)
// b1 f32 [128]      at 69632    (512 B)
// per-warp epilogue tiles: 8 x 16x16 f32 at 70144 (8192 B)
#define LDA 136
#define S_A 0
#define S_B 34816
#define S_B1 69632
#define S_WB 70144
#define S_TOTAL 78336

// Tensor-core (HMMA/wmma) node GEMM: out[m,n] = sum_k A[m,k] * W[n, koff+k]
// fp16 inputs, fp32 accumulate, fp16 output; epilogue from fragments via
// per-warp staging tiles (no block-wide C roundtrip).
// blockIdx.y==0: A=z_src, koff=0, out=g_u (+b1); ==1: A=z_dst, koff=H, out=g_v
__global__ __launch_bounds__(256)
void node_gemm_wmma(const float* __restrict__ zsrc,
                    const float* __restrict__ zdst,
                    const float* __restrict__ W1,
                    const float* __restrict__ b1)
{
    extern __shared__ __align__(16) char smem[];
    __half* As  = (__half*)(smem + S_A);
    __half* Bs  = (__half*)(smem + S_B);
    float*  b1s = (float*)(smem + S_B1);

    const int tid = threadIdx.x;
    const int wid = tid >> 5;
    const int lane = tid & 31;
    const int mbase = blockIdx.x * 128;
    const bool is_src = (blockIdx.y == 0);
    const float* __restrict__ A = is_src ? zsrc : zdst;
    const float* __restrict__ W = W1 + (is_src ? 0 : H);
    __half* __restrict__ out = is_src ? g_u : g_v;

    if (tid < 128) b1s[tid] = is_src ? b1[tid] : 0.f;

    // ---- stage A tile [128 x 128] fp32 -> fp16, padded row-major ----
    #pragma unroll
    for (int it = 0; it < 8; ++it) {
        int c = tid + it * 256;          // 2048 chunks of 8 cols
        int row = c >> 4;
        int col = (c & 15) * 8;
        float4 f0 = make_float4(0.f, 0.f, 0.f, 0.f), f1 = f0;
        int mg = mbase + row;
        if (mg < N_NODES) {
            const float* src = A + (size_t)mg * H + col;
            f0 = *(const float4*)src;
            f1 = *(const float4*)(src + 4);
        }
        __half2 h0 = __float22half2_rn(make_float2(f0.x, f0.y));
        __half2 h1 = __float22half2_rn(make_float2(f0.z, f0.w));
        __half2 h2 = __float22half2_rn(make_float2(f1.x, f1.y));
        __half2 h3 = __float22half2_rn(make_float2(f1.z, f1.w));
        uint4 q;
        q.x = *(uint32_t*)&h0; q.y = *(uint32_t*)&h1;
        q.z = *(uint32_t*)&h2; q.w = *(uint32_t*)&h3;
        *(uint4*)&As[row * LDA + col] = q;
    }
    // ---- stage B tile [128 x 128]: W rows (stride 2H) ----
    #pragma unroll
    for (int it = 0; it < 8; ++it) {
        int c = tid + it * 256;
        int n = c >> 4;
        int col = (c & 15) * 8;
        const float* src = W + (size_t)n * (2 * H) + col;
        float4 f0 = *(const float4*)src;
        float4 f1 = *(const float4*)(src + 4);
        __half2 h0 = __float22half2_rn(make_float2(f0.x, f0.y));
        __half2 h1 = __float22half2_rn(make_float2(f0.z, f0.w));
        __half2 h2 = __float22half2_rn(make_float2(f1.x, f1.y));
        __half2 h3 = __float22half2_rn(make_float2(f1.z, f1.w));
        uint4 q;
        q.x = *(uint32_t*)&h0; q.y = *(uint32_t*)&h1;
        q.z = *(uint32_t*)&h2; q.w = *(uint32_t*)&h3;
        *(uint4*)&Bs[n * LDA + col] = q;
    }
    __syncthreads();

    // ---- wmma compute: warp (wm, wn) owns rows [wm*64, +64), cols [wn*32, +32) ----
    const int wm = wid & 1;
    const int wn = wid >> 1;

    wmma::fragment<wmma::accumulator, 16, 16, 16, float> acc[4][2];
    #pragma unroll
    for (int i = 0; i < 4; ++i)
        #pragma unroll
        for (int j = 0; j < 2; ++j)
            wmma::fill_fragment(acc[i][j], 0.f);

    #pragma unroll
    for (int ks = 0; ks < 128; ks += 16) {
        wmma::fragment<wmma::matrix_a, 16, 16, 16, __half, wmma::row_major> af[4];
        wmma::fragment<wmma::matrix_b, 16, 16, 16, __half, wmma::col_major> bf[2];
        #pragma unroll
        for (int i = 0; i < 4; ++i)
            wmma::load_matrix_sync(af[i], &As[(wm * 64 + 16 * i) * LDA + ks], LDA);
        #pragma unroll
        for (int j = 0; j < 2; ++j)
            wmma::load_matrix_sync(bf[j], &Bs[(wn * 32 + 16 * j) * LDA + ks], LDA);
        #pragma unroll
        for (int i = 0; i < 4; ++i)
            #pragma unroll
            for (int j = 0; j < 2; ++j)
                wmma::mma_sync(acc[i][j], af[i], bf[j], acc[i][j]);
    }

    // ---- epilogue from fragments via per-warp 16x16 staging tile ----
    float* wbuf = (float*)(smem + S_WB) + wid * 256;
    const int r  = lane >> 1;          // 0..15 row within fragment
    const int ch = lane & 1;           // 0/1 -> 8-col half
    #pragma unroll
    for (int i = 0; i < 4; ++i) {
        #pragma unroll
        for (int j = 0; j < 2; ++j) {
            wmma::store_matrix_sync(wbuf, acc[i][j], 16, wmma::mem_row_major);
            __syncwarp();
            const int m = mbase + wm * 64 + 16 * i + r;
            const int c0 = wn * 32 + 16 * j + ch * 8;
            if (m < N_NODES) {
                const float* cp = &wbuf[r * 16 + ch * 8];
                float4 f0 = *(const float4*)cp;
                float4 f1 = *(const float4*)(cp + 4);
                float4 g0 = *(const float4*)&b1s[c0];
                float4 g1 = *(const float4*)&b1s[c0 + 4];
                __half2 h0 = __float22half2_rn(make_float2(f0.x + g0.x, f0.y + g0.y));
                __half2 h1 = __float22half2_rn(make_float2(f0.z + g0.z, f0.w + g0.w));
                __half2 h2 = __float22half2_rn(make_float2(f1.x + g1.x, f1.y + g1.y));
                __half2 h3 = __float22half2_rn(make_float2(f1.z + g1.z, f1.w + g1.w));
                uint4 q;
                q.x = *(uint32_t*)&h0; q.y = *(uint32_t*)&h1;
                q.z = *(uint32_t*)&h2; q.w = *(uint32_t*)&h3;
                *(uint4*)&out[(size_t)m * H + c0] = q;
            }
            __syncwarp();
        }
    }
}

// 4 edges per warp, half2 math: out[e] = W2 . relu(u[row[e]] + v[col[e]]) + b2
__global__ __launch_bounds__(256)
void edge_kernel(const int* __restrict__ eidx,
                 const float* __restrict__ W2,
                 const float* __restrict__ b2,
                 float* __restrict__ out)
{
    const int lane = threadIdx.x & 31;
    const int w = (int)((blockIdx.x * blockDim.x + threadIdx.x) >> 5);
    const int e0 = w * 4;
    if (e0 >= N_EDGES) return;

    const float4 wv = ((const float4*)W2)[lane];
    const __half2 w01 = __floats2half2_rn(wv.x, wv.y);
    const __half2 w23 = __floats2half2_rn(wv.z, wv.w);
    const __half2 zero2 = __floats2half2_rn(0.f, 0.f);

    const int4 r4 = *(const int4*)&eidx[e0];
    const int4 c4 = *(const int4*)&eidx[N_EDGES + e0];

    const uint2* __restrict__ up = (const uint2*)g_u;  // row = 32 uint2
    const uint2* __restrict__ vp = (const uint2*)g_v;

    uint2 ua[4], va[4];
    ua[0] = up[(size_t)r4.x * 32 + lane];
    ua[1] = up[(size_t)r4.y * 32 + lane];
    ua[2] = up[(size_t)r4.z * 32 + lane];
    ua[3] = up[(size_t)r4.w * 32 + lane];
    va[0] = vp[(size_t)c4.x * 32 + lane];
    va[1] = vp[(size_t)c4.y * 32 + lane];
    va[2] = vp[(size_t)c4.z * 32 + lane];
    va[3] = vp[(size_t)c4.w * 32 + lane];

    float s[4];
    #pragma unroll
    for (int i = 0; i < 4; ++i) {
        __half2 a0 = *(const __half2*)&ua[i].x;
        __half2 a1 = *(const __half2*)&ua[i].y;
        __half2 b0 = *(const __half2*)&va[i].x;
        __half2 b1h = *(const __half2*)&va[i].y;
        __half2 t0 = __hmax2(__hadd2(a0, b0), zero2);
        __half2 t1 = __hmax2(__hadd2(a1, b1h), zero2);
        __half2 acch = __hfma2(t0, w01, __hmul2(t1, w23));
        float2 f = __half22float2(acch);
        s[i] = f.x + f.y;
    }

    #pragma unroll
    for (int off = 16; off; off >>= 1) {
        s[0] += __shfl_xor_sync(0xffffffffu, s[0], off);
        s[1] += __shfl_xor_sync(0xffffffffu, s[1], off);
        s[2] += __shfl_xor_sync(0xffffffffu, s[2], off);
        s[3] += __shfl_xor_sync(0xffffffffu, s[3], off);
    }

    if (lane == 0) {
        const float bb = b2[0];
        float4 o = make_float4(s[0] + bb, s[1] + bb, s[2] + bb, s[3] + bb);
        *(float4*)&out[e0] = o;
    }
}

extern "C" void kernel_launch(void* const* d_in, const int* in_sizes, int n_in,
                              void* d_out, int out_size)
{
    const float* zsrc = (const float*)d_in[0];
    const float* zdst = (const float*)d_in[1];
    const int*   eidx = (const int*)d_in[2];
    const float* W1   = (const float*)d_in[3];
    const float* b1   = (const float*)d_in[4];
    const float* W2   = (const float*)d_in[5];
    const float* b2   = (const float*)d_in[6];
    float*       out  = (float*)d_out;

    cudaFuncSetAttribute(node_gemm_wmma, cudaFuncAttributeMaxDynamicSharedMemorySize, S_TOTAL);

    dim3 ggrid((N_NODES + 127) / 128, 2);   // 782 x 2
    node_gemm_wmma<<<ggrid, 256, S_TOTAL>>>(zsrc, zdst, W1, b1);

    const int edges_per_block = (256 / 32) * 4;   // 32 edges/block
    const int eblocks = (N_EDGES + edges_per_block - 1) / edges_per_block;
    edge_kernel<<<eblocks, 256>>>(eidx, W2, b2, out);
}

// round 14
// speedup vs baseline: 2.6776x; 1.0746x over previous
#include <cuda_runtime.h>
#include <cuda_fp16.h>
#include <mma.h>
#include <cstdint>

using namespace nvcuda;

#define N_NODES 100000
#define N_EDGES 1000000
#define H 128

// Scratch: per-node transformed features in fp16 (u = W1_src*z_src + b1, v = W1_dst*z_dst)
__device__ __half g_u[(size_t)N_NODES * H];
__device__ __half g_v[(size_t)N_NODES * H];

// ---- dynamic smem layout ----
// A fp16 [128][136] at 0        (34816 B)
// B fp16 [128][136] at 34816    (34816 B)
// b1 f32 [128]      at 69632    (512 B)
// per-warp epilogue tiles: 8 x 16x16 f32 at 70144 (8192 B)
#define LDA 136
#define S_A 0
#define S_B 34816
#define S_B1 69632
#define S_WB 70144
#define S_TOTAL 78336

// Tensor-core (HMMA/wmma) node GEMM: out[m,n] = sum_k A[m,k] * W[n, koff+k]
// fp16 inputs, fp32 accumulate, fp16 output; epilogue from fragments via
// per-warp staging tiles (no block-wide C roundtrip).
// blockIdx.y==0: A=z_src, koff=0, out=g_u (+b1); ==1: A=z_dst, koff=H, out=g_v
__global__ __launch_bounds__(256)
void node_gemm_wmma(const float* __restrict__ zsrc,
                    const float* __restrict__ zdst,
                    const float* __restrict__ W1,
                    const float* __restrict__ b1)
{
    extern __shared__ __align__(16) char smem[];
    __half* As  = (__half*)(smem + S_A);
    __half* Bs  = (__half*)(smem + S_B);
    float*  b1s = (float*)(smem + S_B1);

    const int tid = threadIdx.x;
    const int wid = tid >> 5;
    const int lane = tid & 31;
    const int mbase = blockIdx.x * 128;
    const bool is_src = (blockIdx.y == 0);
    const float* __restrict__ A = is_src ? zsrc : zdst;
    const float* __restrict__ W = W1 + (is_src ? 0 : H);
    __half* __restrict__ out = is_src ? g_u : g_v;

    if (tid < 128) b1s[tid] = is_src ? b1[tid] : 0.f;

    // ---- stage A tile [128 x 128] fp32 -> fp16, padded row-major ----
    #pragma unroll
    for (int it = 0; it < 8; ++it) {
        int c = tid + it * 256;          // 2048 chunks of 8 cols
        int row = c >> 4;
        int col = (c & 15) * 8;
        float4 f0 = make_float4(0.f, 0.f, 0.f, 0.f), f1 = f0;
        int mg = mbase + row;
        if (mg < N_NODES) {
            const float* src = A + (size_t)mg * H + col;
            f0 = *(const float4*)src;
            f1 = *(const float4*)(src + 4);
        }
        __half2 h0 = __float22half2_rn(make_float2(f0.x, f0.y));
        __half2 h1 = __float22half2_rn(make_float2(f0.z, f0.w));
        __half2 h2 = __float22half2_rn(make_float2(f1.x, f1.y));
        __half2 h3 = __float22half2_rn(make_float2(f1.z, f1.w));
        uint4 q;
        q.x = *(uint32_t*)&h0; q.y = *(uint32_t*)&h1;
        q.z = *(uint32_t*)&h2; q.w = *(uint32_t*)&h3;
        *(uint4*)&As[row * LDA + col] = q;
    }
    // ---- stage B tile [128 x 128]: W rows (stride 2H) ----
    #pragma unroll
    for (int it = 0; it < 8; ++it) {
        int c = tid + it * 256;
        int n = c >> 4;
        int col = (c & 15) * 8;
        const float* src = W + (size_t)n * (2 * H) + col;
        float4 f0 = *(const float4*)src;
        float4 f1 = *(const float4*)(src + 4);
        __half2 h0 = __float22half2_rn(make_float2(f0.x, f0.y));
        __half2 h1 = __float22half2_rn(make_float2(f0.z, f0.w));
        __half2 h2 = __float22half2_rn(make_float2(f1.x, f1.y));
        __half2 h3 = __float22half2_rn(make_float2(f1.z, f1.w));
        uint4 q;
        q.x = *(uint32_t*)&h0; q.y = *(uint32_t*)&h1;
        q.z = *(uint32_t*)&h2; q.w = *(uint32_t*)&h3;
        *(uint4*)&Bs[n * LDA + col] = q;
    }
    __syncthreads();

    // ---- wmma compute: warp (wm, wn) owns rows [wm*64, +64), cols [wn*32, +32) ----
    const int wm = wid & 1;
    const int wn = wid >> 1;

    wmma::fragment<wmma::accumulator, 16, 16, 16, float> acc[4][2];
    #pragma unroll
    for (int i = 0; i < 4; ++i)
        #pragma unroll
        for (int j = 0; j < 2; ++j)
            wmma::fill_fragment(acc[i][j], 0.f);

    #pragma unroll
    for (int ks = 0; ks < 128; ks += 16) {
        wmma::fragment<wmma::matrix_a, 16, 16, 16, __half, wmma::row_major> af[4];
        wmma::fragment<wmma::matrix_b, 16, 16, 16, __half, wmma::col_major> bf[2];
        #pragma unroll
        for (int i = 0; i < 4; ++i)
            wmma::load_matrix_sync(af[i], &As[(wm * 64 + 16 * i) * LDA + ks], LDA);
        #pragma unroll
        for (int j = 0; j < 2; ++j)
            wmma::load_matrix_sync(bf[j], &Bs[(wn * 32 + 16 * j) * LDA + ks], LDA);
        #pragma unroll
        for (int i = 0; i < 4; ++i)
            #pragma unroll
            for (int j = 0; j < 2; ++j)
                wmma::mma_sync(acc[i][j], af[i], bf[j], acc[i][j]);
    }

    // ---- epilogue from fragments via per-warp 16x16 staging tile ----
    float* wbuf = (float*)(smem + S_WB) + wid * 256;
    const int r  = lane >> 1;          // 0..15 row within fragment
    const int ch = lane & 1;           // 0/1 -> 8-col half
    #pragma unroll
    for (int i = 0; i < 4; ++i) {
        #pragma unroll
        for (int j = 0; j < 2; ++j) {
            wmma::store_matrix_sync(wbuf, acc[i][j], 16, wmma::mem_row_major);
            __syncwarp();
            const int m = mbase + wm * 64 + 16 * i + r;
            const int c0 = wn * 32 + 16 * j + ch * 8;
            if (m < N_NODES) {
                const float* cp = &wbuf[r * 16 + ch * 8];
                float4 f0 = *(const float4*)cp;
                float4 f1 = *(const float4*)(cp + 4);
                float4 g0 = *(const float4*)&b1s[c0];
                float4 g1 = *(const float4*)&b1s[c0 + 4];
                __half2 h0 = __float22half2_rn(make_float2(f0.x + g0.x, f0.y + g0.y));
                __half2 h1 = __float22half2_rn(make_float2(f0.z + g0.z, f0.w + g0.w));
                __half2 h2 = __float22half2_rn(make_float2(f1.x + g1.x, f1.y + g1.y));
                __half2 h3 = __float22half2_rn(make_float2(f1.z + g1.z, f1.w + g1.w));
                uint4 q;
                q.x = *(uint32_t*)&h0; q.y = *(uint32_t*)&h1;
                q.z = *(uint32_t*)&h2; q.w = *(uint32_t*)&h3;
                *(uint4*)&out[(size_t)m * H + c0] = q;
            }
            __syncwarp();
        }
    }
}

__device__ __forceinline__ __half2 h2_of(uint32_t u) { return *(__half2*)&u; }

// 8 edges per warp, 16 lanes per edge, LDG.128 row loads.
// out[e] = W2 . relu(u[row[e]] + v[col[e]]) + b2  (u,v fp16)
__global__ __launch_bounds__(256)
void edge_kernel(const int* __restrict__ eidx,
                 const float* __restrict__ W2,
                 const float* __restrict__ b2,
                 float* __restrict__ out)
{
    const int lane = threadIdx.x & 31;
    const int w = (int)((blockIdx.x * blockDim.x + threadIdx.x) >> 5);
    const int e0 = w * 8;
    if (e0 >= N_EDGES) return;

    const int hf  = lane >> 4;        // 0: edges e0..e0+3, 1: e0+4..e0+7
    const int sub = lane & 15;        // 16B chunk within the 256B row

    // per-lane weights: 8 consecutive W2 floats at sub*8 -> 4 half2
    const float4 wa = *(const float4*)&W2[sub * 8];
    const float4 wb = *(const float4*)&W2[sub * 8 + 4];
    const __half2 w0 = __floats2half2_rn(wa.x, wa.y);
    const __half2 w1 = __floats2half2_rn(wa.z, wa.w);
    const __half2 w2h = __floats2half2_rn(wb.x, wb.y);
    const __half2 w3 = __floats2half2_rn(wb.z, wb.w);
    const __half2 zero2 = __float2half2_rn(0.f);
    const float bb = __ldg(b2);

    // this half-warp's 4 edges
    const int4 rr = *(const int4*)&eidx[e0 + hf * 4];
    const int4 cc = *(const int4*)&eidx[N_EDGES + e0 + hf * 4];
    const int ridx[4] = {rr.x, rr.y, rr.z, rr.w};
    const int cidx[4] = {cc.x, cc.y, cc.z, cc.w};

    const uint4* __restrict__ up = (const uint4*)g_u;   // row = 16 uint4
    const uint4* __restrict__ vp = (const uint4*)g_v;

    float res[4];
    #pragma unroll
    for (int t = 0; t < 4; ++t) {
        const uint4 ua = up[(size_t)ridx[t] * 16 + sub];
        const uint4 va = vp[(size_t)cidx[t] * 16 + sub];

        __half2 t0 = __hmax2(__hadd2(h2_of(ua.x), h2_of(va.x)), zero2);
        __half2 t1 = __hmax2(__hadd2(h2_of(ua.y), h2_of(va.y)), zero2);
        __half2 t2 = __hmax2(__hadd2(h2_of(ua.z), h2_of(va.z)), zero2);
        __half2 t3 = __hmax2(__hadd2(h2_of(ua.w), h2_of(va.w)), zero2);

        // 2-deep half2 chains (same error profile as R13), combine in fp32
        __half2 p01 = __hfma2(t1, w1, __hmul2(t0, w0));
        __half2 p23 = __hfma2(t3, w3, __hmul2(t2, w2h));
        float2 f01 = __half22float2(p01);
        float2 f23 = __half22float2(p23);
        float s = (f01.x + f01.y) + (f23.x + f23.y);

        // 16-lane tree reduce (xor within half-warp)
        s += __shfl_xor_sync(0xffffffffu, s, 8);
        s += __shfl_xor_sync(0xffffffffu, s, 4);
        s += __shfl_xor_sync(0xffffffffu, s, 2);
        s += __shfl_xor_sync(0xffffffffu, s, 1);
        res[t] = s + bb;
    }

    if (sub == 0) {
        *(float4*)&out[e0 + hf * 4] = make_float4(res[0], res[1], res[2], res[3]);
    }
}

extern "C" void kernel_launch(void* const* d_in, const int* in_sizes, int n_in,
                              void* d_out, int out_size)
{
    const float* zsrc = (const float*)d_in[0];
    const float* zdst = (const float*)d_in[1];
    const int*   eidx = (const int*)d_in[2];
    const float* W1   = (const float*)d_in[3];
    const float* b1   = (const float*)d_in[4];
    const float* W2   = (const float*)d_in[5];
    const float* b2   = (const float*)d_in[6];
    float*       out  = (float*)d_out;

    cudaFuncSetAttribute(node_gemm_wmma, cudaFuncAttributeMaxDynamicSharedMemorySize, S_TOTAL);

    dim3 ggrid((N_NODES + 127) / 128, 2);   // 782 x 2
    node_gemm_wmma<<<ggrid, 256, S_TOTAL>>>(zsrc, zdst, W1, b1);

    const int edges_per_block = (256 / 32) * 8;   // 64 edges/block
    const int eblocks = (N_EDGES + edges_per_block - 1) / edges_per_block;
    edge_kernel<<<eblocks, 256>>>(eidx, W2, b2, out);
}

// round 15
// speedup vs baseline: 2.8386x; 1.0601x over previous
#include <cuda_runtime.h>
#include <cuda_fp16.h>
#include <mma.h>
#include <cstdint>

using namespace nvcuda;

#define N_NODES 100000
#define N_EDGES 1000000
#define H 128

// Scratch: per-node transformed features in fp16 (u = W1_src*z_src + b1, v = W1_dst*z_dst)
__device__ __half g_u[(size_t)N_NODES * H];
__device__ __half g_v[(size_t)N_NODES * H];

#define LDA 136
// Pre-converted W1 halves, already in the padded smem-image layout [n*LDA + k]
__device__ __half g_w1h[2][128 * LDA];

// ---- dynamic smem layout ----
// A fp16 [128][136] at 0        (34816 B)
// B fp16 [128][136] at 34816    (34816 B)
// b1 f32 [128]      at 69632    (512 B)
// epilogue per-warp tiles reuse the A region after a __syncthreads()
#define S_A 0
#define S_B 34816
#define S_B1 69632
#define S_TOTAL 70144

// One-shot W1 fp32 -> fp16 into padded image. 128 blocks x 256 thr = 32768 elems.
__global__ __launch_bounds__(256)
void convert_w1_kernel(const float* __restrict__ W1)
{
    int e = blockIdx.x * 256 + threadIdx.x;      // 0..32767
    int h = e >> 14;                             // 0: src half, 1: dst half
    int rem = e & 16383;
    int n = rem >> 7;
    int k = rem & 127;
    g_w1h[h][n * LDA + k] = __float2half_rn(W1[n * (2 * H) + h * H + k]);
}

// Tensor-core (HMMA/wmma) node GEMM: out[m,n] = sum_k A[m,k] * W[n, koff+k]
// fp16 inputs, fp32 accumulate, fp16 output. B staged via cp.async from the
// pre-converted fp16 image; epilogue reuses the A smem region.
// blockIdx.y==0: A=z_src, out=g_u (+b1); ==1: A=z_dst, out=g_v
__global__ __launch_bounds__(256)
void node_gemm_wmma(const float* __restrict__ zsrc,
                    const float* __restrict__ zdst,
                    const float* __restrict__ b1)
{
    extern __shared__ __align__(16) char smem[];
    __half* As  = (__half*)(smem + S_A);
    __half* Bs  = (__half*)(smem + S_B);
    float*  b1s = (float*)(smem + S_B1);

    const int tid = threadIdx.x;
    const int wid = tid >> 5;
    const int lane = tid & 31;
    const int mbase = blockIdx.x * 128;
    const bool is_src = (blockIdx.y == 0);
    const float* __restrict__ A = is_src ? zsrc : zdst;
    const __half* __restrict__ Bg = g_w1h[is_src ? 0 : 1];
    __half* __restrict__ out = is_src ? g_u : g_v;

    if (tid < 128) b1s[tid] = is_src ? b1[tid] : 0.f;

    // ---- stage B tile via cp.async (16B chunks, overlaps A conversion) ----
    #pragma unroll
    for (int it = 0; it < 8; ++it) {
        int c = tid + it * 256;              // 2048 chunks of 8 halves
        int row = c >> 4;
        int chunk = (c & 15) * 8;
        uint32_t dst = (uint32_t)__cvta_generic_to_shared(&Bs[row * LDA + chunk]);
        const __half* src = &Bg[row * LDA + chunk];
        asm volatile("cp.async.ca.shared.global [%0], [%1], 16;" :: "r"(dst), "l"(src));
    }
    asm volatile("cp.async.commit_group;" ::: "memory");

    // ---- stage A tile [128 x 128] fp32 -> fp16, padded row-major ----
    #pragma unroll
    for (int it = 0; it < 8; ++it) {
        int c = tid + it * 256;          // 2048 chunks of 8 cols
        int row = c >> 4;
        int col = (c & 15) * 8;
        float4 f0 = make_float4(0.f, 0.f, 0.f, 0.f), f1 = f0;
        int mg = mbase + row;
        if (mg < N_NODES) {
            const float* src = A + (size_t)mg * H + col;
            f0 = *(const float4*)src;
            f1 = *(const float4*)(src + 4);
        }
        __half2 h0 = __float22half2_rn(make_float2(f0.x, f0.y));
        __half2 h1 = __float22half2_rn(make_float2(f0.z, f0.w));
        __half2 h2 = __float22half2_rn(make_float2(f1.x, f1.y));
        __half2 h3 = __float22half2_rn(make_float2(f1.z, f1.w));
        uint4 q;
        q.x = *(uint32_t*)&h0; q.y = *(uint32_t*)&h1;
        q.z = *(uint32_t*)&h2; q.w = *(uint32_t*)&h3;
        *(uint4*)&As[row * LDA + col] = q;
    }

    asm volatile("cp.async.wait_group 0;" ::: "memory");
    __syncthreads();

    // ---- wmma compute: warp (wm, wn) owns rows [wm*64, +64), cols [wn*32, +32) ----
    const int wm = wid & 1;
    const int wn = wid >> 1;

    wmma::fragment<wmma::accumulator, 16, 16, 16, float> acc[4][2];
    #pragma unroll
    for (int i = 0; i < 4; ++i)
        #pragma unroll
        for (int j = 0; j < 2; ++j)
            wmma::fill_fragment(acc[i][j], 0.f);

    #pragma unroll
    for (int ks = 0; ks < 128; ks += 16) {
        wmma::fragment<wmma::matrix_a, 16, 16, 16, __half, wmma::row_major> af[4];
        wmma::fragment<wmma::matrix_b, 16, 16, 16, __half, wmma::col_major> bf[2];
        #pragma unroll
        for (int i = 0; i < 4; ++i)
            wmma::load_matrix_sync(af[i], &As[(wm * 64 + 16 * i) * LDA + ks], LDA);
        #pragma unroll
        for (int j = 0; j < 2; ++j)
            wmma::load_matrix_sync(bf[j], &Bs[(wn * 32 + 16 * j) * LDA + ks], LDA);
        #pragma unroll
        for (int i = 0; i < 4; ++i)
            #pragma unroll
            for (int j = 0; j < 2; ++j)
                wmma::mma_sync(acc[i][j], af[i], bf[j], acc[i][j]);
    }

    __syncthreads();   // everyone done reading As/Bs; epilogue reuses A region

    // ---- epilogue from fragments via per-warp 16x16 staging tile (in A region) ----
    float* wbuf = (float*)(smem) + wid * 256;
    const int r  = lane >> 1;          // 0..15 row within fragment
    const int ch = lane & 1;           // 0/1 -> 8-col half
    #pragma unroll
    for (int i = 0; i < 4; ++i) {
        #pragma unroll
        for (int j = 0; j < 2; ++j) {
            wmma::store_matrix_sync(wbuf, acc[i][j], 16, wmma::mem_row_major);
            __syncwarp();
            const int m = mbase + wm * 64 + 16 * i + r;
            const int c0 = wn * 32 + 16 * j + ch * 8;
            if (m < N_NODES) {
                const float* cp = &wbuf[r * 16 + ch * 8];
                float4 f0 = *(const float4*)cp;
                float4 f1 = *(const float4*)(cp + 4);
                float4 g0 = *(const float4*)&b1s[c0];
                float4 g1 = *(const float4*)&b1s[c0 + 4];
                __half2 h0 = __float22half2_rn(make_float2(f0.x + g0.x, f0.y + g0.y));
                __half2 h1 = __float22half2_rn(make_float2(f0.z + g0.z, f0.w + g0.w));
                __half2 h2 = __float22half2_rn(make_float2(f1.x + g1.x, f1.y + g1.y));
                __half2 h3 = __float22half2_rn(make_float2(f1.z + g1.z, f1.w + g1.w));
                uint4 q;
                q.x = *(uint32_t*)&h0; q.y = *(uint32_t*)&h1;
                q.z = *(uint32_t*)&h2; q.w = *(uint32_t*)&h3;
                *(uint4*)&out[(size_t)m * H + c0] = q;
            }
            __syncwarp();
        }
    }
}

__device__ __forceinline__ __half2 h2_of(uint32_t u) { return *(__half2*)&u; }

// 8 edges per warp, 16 lanes per edge, LDG.128 row loads.
// out[e] = W2 . relu(u[row[e]] + v[col[e]]) + b2  (u,v fp16)
__global__ __launch_bounds__(256)
void edge_kernel(const int* __restrict__ eidx,
                 const float* __restrict__ W2,
                 const float* __restrict__ b2,
                 float* __restrict__ out)
{
    const int lane = threadIdx.x & 31;
    const int w = (int)((blockIdx.x * blockDim.x + threadIdx.x) >> 5);
    const int e0 = w * 8;
    if (e0 >= N_EDGES) return;

    const int hf  = lane >> 4;        // 0: edges e0..e0+3, 1: e0+4..e0+7
    const int sub = lane & 15;        // 16B chunk within the 256B row

    // per-lane weights: 8 consecutive W2 floats at sub*8 -> 4 half2
    const float4 wa = *(const float4*)&W2[sub * 8];
    const float4 wb = *(const float4*)&W2[sub * 8 + 4];
    const __half2 w0 = __floats2half2_rn(wa.x, wa.y);
    const __half2 w1 = __floats2half2_rn(wa.z, wa.w);
    const __half2 w2h = __floats2half2_rn(wb.x, wb.y);
    const __half2 w3 = __floats2half2_rn(wb.z, wb.w);
    const __half2 zero2 = __float2half2_rn(0.f);
    const float bb = __ldg(b2);

    // this half-warp's 4 edges
    const int4 rr = *(const int4*)&eidx[e0 + hf * 4];
    const int4 cc = *(const int4*)&eidx[N_EDGES + e0 + hf * 4];
    const int ridx[4] = {rr.x, rr.y, rr.z, rr.w};
    const int cidx[4] = {cc.x, cc.y, cc.z, cc.w};

    const uint4* __restrict__ up = (const uint4*)g_u;   // row = 16 uint4
    const uint4* __restrict__ vp = (const uint4*)g_v;

    float res[4];
    #pragma unroll
    for (int t = 0; t < 4; ++t) {
        const uint4 ua = up[(size_t)ridx[t] * 16 + sub];
        const uint4 va = vp[(size_t)cidx[t] * 16 + sub];

        __half2 t0 = __hmax2(__hadd2(h2_of(ua.x), h2_of(va.x)), zero2);
        __half2 t1 = __hmax2(__hadd2(h2_of(ua.y), h2_of(va.y)), zero2);
        __half2 t2 = __hmax2(__hadd2(h2_of(ua.z), h2_of(va.z)), zero2);
        __half2 t3 = __hmax2(__hadd2(h2_of(ua.w), h2_of(va.w)), zero2);

        // 2-deep half2 chains, combine in fp32
        __half2 p01 = __hfma2(t1, w1, __hmul2(t0, w0));
        __half2 p23 = __hfma2(t3, w3, __hmul2(t2, w2h));
        float2 f01 = __half22float2(p01);
        float2 f23 = __half22float2(p23);
        float s = (f01.x + f01.y) + (f23.x + f23.y);

        // 16-lane tree reduce (xor within half-warp)
        s += __shfl_xor_sync(0xffffffffu, s, 8);
        s += __shfl_xor_sync(0xffffffffu, s, 4);
        s += __shfl_xor_sync(0xffffffffu, s, 2);
        s += __shfl_xor_sync(0xffffffffu, s, 1);
        res[t] = s + bb;
    }

    if (sub == 0) {
        *(float4*)&out[e0 + hf * 4] = make_float4(res[0], res[1], res[2], res[3]);
    }
}

extern "C" void kernel_launch(void* const* d_in, const int* in_sizes, int n_in,
                              void* d_out, int out_size)
{
    const float* zsrc = (const float*)d_in[0];
    const float* zdst = (const float*)d_in[1];
    const int*   eidx = (const int*)d_in[2];
    const float* W1   = (const float*)d_in[3];
    const float* b1   = (const float*)d_in[4];
    const float* W2   = (const float*)d_in[5];
    const float* b2   = (const float*)d_in[6];
    float*       out  = (float*)d_out;

    cudaFuncSetAttribute(node_gemm_wmma, cudaFuncAttributeMaxDynamicSharedMemorySize, S_TOTAL);

    convert_w1_kernel<<<128, 256>>>(W1);

    dim3 ggrid((N_NODES + 127) / 128, 2);   // 782 x 2
    node_gemm_wmma<<<ggrid, 256, S_TOTAL>>>(zsrc, zdst, b1);

    const int edges_per_block = (256 / 32) * 8;   // 64 edges/block
    const int eblocks = (N_EDGES + edges_per_block - 1) / edges_per_block;
    edge_kernel<<<eblocks, 256>>>(eidx, W2, b2, out);
}